// round 1
// baseline (speedup 1.0000x reference)
#include <cuda_runtime.h>

#define B 8
#define N 2048
#define F 64
#define MAXNNZ 256
#define BN (B*N)  // 16384
#define LRELU_SLOPE 0.2f

// ---- scratch (static device arrays; re-initialized every launch) ----
__device__ float  g_h[BN*F];                       // 4 MB   h = input @ W
__device__ float  g_f1[BN];
__device__ float  g_f2[BN];
__device__ float  g_Dsum[BN];                      // sum of expm1 terms per column
__device__ float  g_invD[BN];
__device__ float  g_c[B*F];                        // per-batch constant row
__device__ int    g_nnz[BN];
__device__ float2 g_pairs[(size_t)BN*MAXNNZ];      // 33.5 MB (j as int bits, p)

// ---------------- init: zero D accumulator ----------------
__global__ void k_init() {
    int idx = blockIdx.x * blockDim.x + threadIdx.x;
    if (idx < BN) g_Dsum[idx] = 0.f;
}

// ---------------- A: h = input@W, f1 = h@a1, f2 = h@a2 ----------------
// block = 512 threads = 8 rows x 64 feature-threads
__global__ void k_hproj(const float* __restrict__ in, const float* __restrict__ W,
                        const float* __restrict__ a1, const float* __restrict__ a2) {
    __shared__ float Ws[F*F];
    __shared__ float a1s[F], a2s[F];
    __shared__ float ins[8*F];
    __shared__ float hs[8*F];
    int tid = threadIdx.x;
    int rowBase = blockIdx.x * 8;

    for (int t = tid; t < F*F; t += 512) Ws[t] = W[t];
    if (tid < F) { a1s[tid] = a1[tid]; a2s[tid] = a2[tid]; }
    ins[tid] = in[rowBase*F + tid];
    __syncthreads();

    int r = tid >> 6, o = tid & 63;
    float acc = 0.f;
#pragma unroll
    for (int f = 0; f < F; f++) acc += ins[r*F + f] * Ws[f*F + o];
    g_h[(rowBase + r)*F + o] = acc;
    hs[tid] = acc;
    __syncthreads();

    int w = tid >> 5, lane = tid & 31;
    if (w < 8) {
        float v1 = hs[w*F + lane]*a1s[lane] + hs[w*F + lane + 32]*a1s[lane + 32];
        float v2 = hs[w*F + lane]*a2s[lane] + hs[w*F + lane + 32]*a2s[lane + 32];
#pragma unroll
        for (int off = 16; off; off >>= 1) {
            v1 += __shfl_down_sync(0xffffffffu, v1, off);
            v2 += __shfl_down_sync(0xffffffffu, v2, off);
        }
        if (lane == 0) { g_f1[rowBase + w] = v1; g_f2[rowBase + w] = v2; }
    }
}

// ---------------- B: stream adj once; compact nonzeros; accumulate D ----------------
// block = 512 threads = 16 warps; each warp owns one full adjacency row.
__global__ void k_scan(const float* __restrict__ adj) {
    __shared__ float  Dpart[N];
    __shared__ float4 f2s4[N/4];
    int tid = threadIdx.x;
    int b  = blockIdx.x >> 7;            // 128 blocks per batch
    int i0 = (blockIdx.x & 127) * 16;

    for (int t = tid; t < N; t += 512) Dpart[t] = 0.f;
    float* f2s = (float*)f2s4;
    for (int t = tid; t < N; t += 512) f2s[t] = g_f2[b*N + t];
    __syncthreads();

    int w = tid >> 5, lane = tid & 31;
    int i   = i0 + w;
    int row = b*N + i;
    float f1i = g_f1[row];
    const float4* arow = (const float4*)(adj + (size_t)row * N);
    unsigned lmask = (1u << lane) - 1u;
    int nnz = 0;

    for (int t = lane; t < N/4; t += 32) {
        float4 a   = arow[t];
        float4 f2v = f2s4[t];
#pragma unroll
        for (int k = 0; k < 4; k++) {
            float av = (k==0)?a.x:(k==1)?a.y:(k==2)?a.z:a.w;
            float fv = (k==0)?f2v.x:(k==1)?f2v.y:(k==2)?f2v.z:f2v.w;
            bool pred = (av != 0.f);
            unsigned m = __ballot_sync(0xffffffffu, pred);
            if (m) {
                if (pred) {
                    float e = f1i + fv;
                    e = (e >= 0.f) ? e : LRELU_SLOPE * e;
                    float p = __expf(av * e) - 1.f;   // expm1(adj * lrelu(...))
                    int slot = nnz + __popc(m & lmask);
                    if (slot < MAXNNZ) {
                        int j = 4*t + k;
                        g_pairs[(size_t)row*MAXNNZ + slot] =
                            make_float2(__int_as_float(j), p);
                    }
                    atomicAdd(&Dpart[4*t + k], p);
                }
                nnz += __popc(m);
            }
        }
    }
    if (lane == 0) g_nnz[row] = min(nnz, MAXNNZ);
    __syncthreads();
    for (int t = tid; t < N; t += 512) atomicAdd(&g_Dsum[b*N + t], Dpart[t]);
}

// ---------------- C1: invD = 1/(N + Dsum) ----------------
__global__ void k_invd() {
    int idx = blockIdx.x * blockDim.x + threadIdx.x;
    if (idx < BN) g_invD[idx] = 1.f / ((float)N + g_Dsum[idx]);
}

// ---------------- C2: c[b,o] = sum_j invD[b,j] * h[b,j,o] ----------------
__global__ void k_cvec() {
    __shared__ float part[512];
    int tid = threadIdx.x;
    int b = blockIdx.x;
    int jj = tid >> 6, o = tid & 63;
    float acc = 0.f;
    for (int j = jj; j < N; j += 8)
        acc += g_invD[b*N + j] * g_h[(size_t)(b*N + j)*F + o];
    part[tid] = acc;
    __syncthreads();
    if (tid < 64) {
        float s = 0.f;
#pragma unroll
        for (int q = 0; q < 8; q++) s += part[q*64 + tid];
        g_c[b*F + tid] = s;
    }
}

// ---------------- D: sparse gather + epilogue (bias, residual, ELU) ----------------
// block = 256 threads = 8 warps; one warp per output row; lane o covers o, o+32.
__global__ void k_out(const float* __restrict__ in, const float* __restrict__ bias,
                      float* __restrict__ out) {
    int w = threadIdx.x >> 5, lane = threadIdx.x & 31;
    int row = blockIdx.x * 8 + w;
    int b = row >> 11, i = row & (N - 1);
    int nnz = g_nnz[row];
    const float2* pbase = g_pairs + (size_t)row * MAXNNZ;
    const float* invD = g_invD + b*N;
    const float* hb   = g_h + (size_t)b*N*F;

    float acc0 = 0.f, acc1 = 0.f;
    for (int k0 = 0; k0 < nnz; k0 += 32) {
        float2 pr = make_float2(0.f, 0.f);
        if (k0 + lane < nnz) pr = pbase[k0 + lane];
        int cnt = min(32, nnz - k0);
        for (int m = 0; m < cnt; m++) {
            int   j = __float_as_int(__shfl_sync(0xffffffffu, pr.x, m));
            float p = __shfl_sync(0xffffffffu, pr.y, m);
            float wgt = p * invD[j];
            const float* hr = hb + j*F;
            acc0 += wgt * hr[lane];
            acc1 += wgt * hr[lane + 32];
        }
    }

    int oidx = row * F;
    float v0 = acc0 + g_c[b*F + lane]      + bias[i*F + lane]      + in[oidx + lane];
    float v1 = acc1 + g_c[b*F + lane + 32] + bias[i*F + lane + 32] + in[oidx + lane + 32];
    out[oidx + lane]      = (v0 > 0.f) ? v0 : expm1f(v0);
    out[oidx + lane + 32] = (v1 > 0.f) ? v1 : expm1f(v1);
}

// ---------------- launch ----------------
extern "C" void kernel_launch(void* const* d_in, const int* in_sizes, int n_in,
                              void* d_out, int out_size) {
    const float* input = (const float*)d_in[0];
    const float* adj   = (const float*)d_in[1];
    const float* W     = (const float*)d_in[2];
    const float* a1    = (const float*)d_in[3];
    const float* a2    = (const float*)d_in[4];
    const float* bias  = (const float*)d_in[5];
    float* out = (float*)d_out;

    k_init <<<(BN + 1023)/1024, 1024>>>();
    k_hproj<<<BN/8,  512>>>(input, W, a1, a2);
    k_scan <<<BN/16, 512>>>(adj);
    k_invd <<<(BN + 1023)/1024, 1024>>>();
    k_cvec <<<B,     512>>>();
    k_out  <<<BN/8,  256>>>(input, bias, out);
}

// round 2
// speedup vs baseline: 1.4757x; 1.4757x over previous
#include <cuda_runtime.h>

#define B 8
#define N 2048
#define F 64
#define MAXNNZ 256
#define BN (B*N)  // 16384
#define LRELU_SLOPE 0.2f

// ---- scratch (static device arrays; re-initialized every launch) ----
__device__ float  g_h[BN*F];                       // 4 MB   h = input @ W
__device__ float  g_f1[BN];
__device__ float  g_f2[BN];
__device__ float  g_Dsum[BN];                      // sum of expm1 terms per column
__device__ float  g_invD[BN];
__device__ float  g_c[B*F];                        // per-batch constant row
__device__ int    g_nnz[BN];
__device__ float2 g_pairs[(size_t)BN*MAXNNZ];      // (j as int bits, p), zero-padded to %8

// ---------------- A: h = input@W, f1 = h@a1, f2 = h@a2 (+ zero accumulators) ----
// block = 512 threads = 8 rows x 64 feature-threads; grid = BN/8 = 2048
__global__ void k_hproj(const float* __restrict__ in, const float* __restrict__ W,
                        const float* __restrict__ a1, const float* __restrict__ a2) {
    __shared__ float Ws[F*F];
    __shared__ float a1s[F], a2s[F];
    __shared__ float ins[8*F];
    __shared__ float hs[8*F];
    int tid = threadIdx.x;
    int rowBase = blockIdx.x * 8;

    // fold accumulator zeroing into this kernel (removes k_init / part of k_invd)
    if (blockIdx.x < 32) g_Dsum[blockIdx.x * 512 + tid] = 0.f;
    if (blockIdx.x == 32 && tid < B*F) g_c[tid] = 0.f;

    for (int t = tid; t < F*F; t += 512) Ws[t] = W[t];
    if (tid < F) { a1s[tid] = a1[tid]; a2s[tid] = a2[tid]; }
    ins[tid] = in[rowBase*F + tid];
    __syncthreads();

    int r = tid >> 6, o = tid & 63;
    float acc = 0.f;
#pragma unroll
    for (int f = 0; f < F; f++) acc += ins[r*F + f] * Ws[f*F + o];
    g_h[(rowBase + r)*F + o] = acc;
    hs[tid] = acc;
    __syncthreads();

    int w = tid >> 5, lane = tid & 31;
    if (w < 8) {
        float v1 = hs[w*F + lane]*a1s[lane] + hs[w*F + lane + 32]*a1s[lane + 32];
        float v2 = hs[w*F + lane]*a2s[lane] + hs[w*F + lane + 32]*a2s[lane + 32];
#pragma unroll
        for (int off = 16; off; off >>= 1) {
            v1 += __shfl_down_sync(0xffffffffu, v1, off);
            v2 += __shfl_down_sync(0xffffffffu, v2, off);
        }
        if (lane == 0) { g_f1[rowBase + w] = v1; g_f2[rowBase + w] = v2; }
    }
}

// ---------------- B: stream adj once; compact nonzeros; accumulate D ----------------
// block = 512 threads = 16 warps; each warp owns one full adjacency row.
__global__ void k_scan(const float* __restrict__ adj) {
    __shared__ float  Dpart[N];
    __shared__ float4 f2s4[N/4];
    int tid = threadIdx.x;
    int b  = blockIdx.x >> 7;            // 128 blocks per batch
    int i0 = (blockIdx.x & 127) * 16;

    for (int t = tid; t < N; t += 512) Dpart[t] = 0.f;
    float* f2s = (float*)f2s4;
    for (int t = tid; t < N; t += 512) f2s[t] = g_f2[b*N + t];
    __syncthreads();

    int w = tid >> 5, lane = tid & 31;
    int i   = i0 + w;
    int row = b*N + i;
    float f1i = g_f1[row];
    const float4* arow = (const float4*)(adj + (size_t)row * N);
    float2* pbase = g_pairs + (size_t)row * MAXNNZ;
    unsigned lmask = (1u << lane) - 1u;
    int nnz = 0;

    for (int t = lane; t < N/4; t += 32) {
        float4 a   = arow[t];
        float4 f2v = f2s4[t];
#pragma unroll
        for (int k = 0; k < 4; k++) {
            float av = (k==0)?a.x:(k==1)?a.y:(k==2)?a.z:a.w;
            float fv = (k==0)?f2v.x:(k==1)?f2v.y:(k==2)?f2v.z:f2v.w;
            bool pred = (av != 0.f);
            unsigned m = __ballot_sync(0xffffffffu, pred);
            if (m) {
                if (pred) {
                    float e = f1i + fv;
                    e = (e >= 0.f) ? e : LRELU_SLOPE * e;
                    float p = __expf(av * e) - 1.f;   // expm1(adj * lrelu(...))
                    int slot = nnz + __popc(m & lmask);
                    if (slot < MAXNNZ) {
                        int j = 4*t + k;
                        pbase[slot] = make_float2(__int_as_float(j), p);
                    }
                    atomicAdd(&Dpart[4*t + k], p);
                }
                nnz += __popc(m);
            }
        }
    }
    nnz = min(nnz, MAXNNZ);
    if (lane == 0) g_nnz[row] = nnz;
    // zero-pad pairs to a multiple of 8 so k_out can run a fixed-unroll loop
    int npad = (nnz + 7) & ~7;
    if (nnz + lane < npad) pbase[nnz + lane] = make_float2(0.f, 0.f);

    __syncthreads();
    for (int t = tid; t < N; t += 512) atomicAdd(&g_Dsum[b*N + t], Dpart[t]);
}

// ---------------- C: invD = 1/(N+Dsum); c[b,o] += sum_j invD[j]*h[j,o] ----------------
// grid = 256 blocks (32 per batch, 64 j-rows each); 512 threads = 8 j x 64 o
__global__ void k_cvec() {
    __shared__ float inv_s[64];
    __shared__ float part[512];
    int tid = threadIdx.x;
    int b  = blockIdx.x >> 5;
    int j0 = (blockIdx.x & 31) * 64;

    if (tid < 64) {
        float v = 1.f / ((float)N + g_Dsum[b*N + j0 + tid]);
        g_invD[b*N + j0 + tid] = v;
        inv_s[tid] = v;
    }
    __syncthreads();

    int r = tid >> 6, o = tid & 63;
    float acc = 0.f;
#pragma unroll
    for (int q = 0; q < 8; q++) {
        int jj = q*8 + r;
        acc += inv_s[jj] * g_h[(size_t)(b*N + j0 + jj)*F + o];
    }
    part[tid] = acc;
    __syncthreads();
    if (tid < 64) {
        float s = 0.f;
#pragma unroll
        for (int q = 0; q < 8; q++) s += part[q*64 + tid];
        atomicAdd(&g_c[b*F + tid], s);
    }
}

// ---------------- D: sparse gather + epilogue (bias, residual, ELU) ----------------
// block = 256 threads = 8 warps; one warp per row; lane holds float2 of features.
__global__ void k_out(const float* __restrict__ in, const float* __restrict__ bias,
                      float* __restrict__ out) {
    int w = threadIdx.x >> 5, lane = threadIdx.x & 31;
    int row = blockIdx.x * 8 + w;
    int b = row >> 11, i = row & (N - 1);
    int npad = (g_nnz[row] + 7) & ~7;
    const float2* __restrict__ pbase = g_pairs + (size_t)row * MAXNNZ;
    const float*  __restrict__ invD  = g_invD + b*N;
    const float2* __restrict__ hb2   = (const float2*)(g_h + (size_t)b*N*F);

    float accx = 0.f, accy = 0.f;
    for (int k0 = 0; k0 < npad; k0 += 8) {
#pragma unroll
        for (int u = 0; u < 8; u++) {
            float2 pr = pbase[k0 + u];                 // warp-uniform (1 sector)
            int   j   = __float_as_int(pr.x);
            float wgt = pr.y * invD[j];
            float2 hv = hb2[j*32 + lane];              // coalesced 256B gather
            accx += wgt * hv.x;
            accy += wgt * hv.y;
        }
    }

    int oidx = row * F + 2*lane;
    float v0 = accx + g_c[b*F + 2*lane]     + bias[i*F + 2*lane]     + in[oidx];
    float v1 = accy + g_c[b*F + 2*lane + 1] + bias[i*F + 2*lane + 1] + in[oidx + 1];
    float2 res;
    res.x = (v0 > 0.f) ? v0 : expm1f(v0);
    res.y = (v1 > 0.f) ? v1 : expm1f(v1);
    *(float2*)(out + oidx) = res;
}

// ---------------- launch ----------------
extern "C" void kernel_launch(void* const* d_in, const int* in_sizes, int n_in,
                              void* d_out, int out_size) {
    const float* input = (const float*)d_in[0];
    const float* adj   = (const float*)d_in[1];
    const float* W     = (const float*)d_in[2];
    const float* a1    = (const float*)d_in[3];
    const float* a2    = (const float*)d_in[4];
    const float* bias  = (const float*)d_in[5];
    float* out = (float*)d_out;

    k_hproj<<<BN/8,  512>>>(input, W, a1, a2);
    k_scan <<<BN/16, 512>>>(adj);
    k_cvec <<<B*32,  512>>>();
    k_out  <<<BN/8,  256>>>(input, bias, out);
}

// round 3
// speedup vs baseline: 1.6670x; 1.1296x over previous
#include <cuda_runtime.h>

#define B 8
#define N 2048
#define F 64
#define MAXNNZ 256
#define BN (B*N)  // 16384
#define LRELU_SLOPE 0.2f

// ---- scratch (static device arrays; re-initialized every launch) ----
__device__ float  g_h[BN*F];                       // 4 MB   h = input @ W
__device__ float  g_f1[BN];
__device__ float  g_f2[BN];
__device__ float  g_Dsum[BN];                      // sum of expm1 terms per column
__device__ float  g_invD[BN];
__device__ float  g_c[B*F];                        // per-batch constant row
__device__ int    g_nnz[BN];
__device__ float2 g_pairs[(size_t)BN*MAXNNZ];      // (j as int bits, p), zero-padded to %8

// ---------------- A: h = input@W, f1 = h@a1, f2 = h@a2 (+ zero accumulators) ----
__global__ void k_hproj(const float* __restrict__ in, const float* __restrict__ W,
                        const float* __restrict__ a1, const float* __restrict__ a2) {
    __shared__ float Ws[F*F];
    __shared__ float a1s[F], a2s[F];
    __shared__ float ins[8*F];
    __shared__ float hs[8*F];
    int tid = threadIdx.x;
    int rowBase = blockIdx.x * 8;

    if (blockIdx.x < 32) g_Dsum[blockIdx.x * 512 + tid] = 0.f;
    if (blockIdx.x == 32 && tid < B*F) g_c[tid] = 0.f;

    for (int t = tid; t < F*F; t += 512) Ws[t] = W[t];
    if (tid < F) { a1s[tid] = a1[tid]; a2s[tid] = a2[tid]; }
    ins[tid] = in[rowBase*F + tid];
    __syncthreads();

    int r = tid >> 6, o = tid & 63;
    float acc = 0.f;
#pragma unroll
    for (int f = 0; f < F; f++) acc += ins[r*F + f] * Ws[f*F + o];
    g_h[(rowBase + r)*F + o] = acc;
    hs[tid] = acc;
    __syncthreads();

    int w = tid >> 5, lane = tid & 31;
    if (w < 8) {
        float v1 = hs[w*F + lane]*a1s[lane] + hs[w*F + lane + 32]*a1s[lane + 32];
        float v2 = hs[w*F + lane]*a2s[lane] + hs[w*F + lane + 32]*a2s[lane + 32];
#pragma unroll
        for (int off = 16; off; off >>= 1) {
            v1 += __shfl_down_sync(0xffffffffu, v1, off);
            v2 += __shfl_down_sync(0xffffffffu, v2, off);
        }
        if (lane == 0) { g_f1[rowBase + w] = v1; g_f2[rowBase + w] = v2; }
    }
}

// ---------------- B: stream adj once; compact nonzeros; accumulate D ----------------
// block = 512 threads = 16 warps; each warp owns one row. Adj loads software-pipelined.
__global__ void k_scan(const float* __restrict__ adj) {
    __shared__ float  Dpart[N];
    __shared__ float4 f2s4[N/4];
    int tid = threadIdx.x;
    int b  = blockIdx.x >> 7;
    int i0 = (blockIdx.x & 127) * 16;

    for (int t = tid; t < N; t += 512) Dpart[t] = 0.f;
    float* f2s = (float*)f2s4;
    for (int t = tid; t < N; t += 512) f2s[t] = g_f2[b*N + t];
    __syncthreads();

    int w = tid >> 5, lane = tid & 31;
    int row = b*N + i0 + w;
    float f1i = g_f1[row];
    const float4* __restrict__ arow = (const float4*)(adj + (size_t)row * N);
    float2* pbase = g_pairs + (size_t)row * MAXNNZ;
    unsigned lmask = (1u << lane) - 1u;
    int nnz = 0;

    int t = lane;
    float4 a = arow[t];                       // prefetch stage 0
#pragma unroll 1
    for (int it = 0; it < 16; it++) {
        float4 anext;
        if (it < 15) anext = arow[t + 32];    // overlap next load with processing
        float4 f2v = f2s4[t];
#pragma unroll
        for (int k = 0; k < 4; k++) {
            float av = (k==0)?a.x:(k==1)?a.y:(k==2)?a.z:a.w;
            float fv = (k==0)?f2v.x:(k==1)?f2v.y:(k==2)?f2v.z:f2v.w;
            bool pred = (av != 0.f);
            unsigned m = __ballot_sync(0xffffffffu, pred);
            if (pred) {
                float e = f1i + fv;
                e = (e >= 0.f) ? e : LRELU_SLOPE * e;
                float p = __expf(av * e) - 1.f;
                int slot = nnz + __popc(m & lmask);
                if (slot < MAXNNZ)
                    pbase[slot] = make_float2(__int_as_float(4*t + k), p);
                atomicAdd(&Dpart[4*t + k], p);
            }
            nnz += __popc(m);
        }
        a = anext; t += 32;
    }
    nnz = min(nnz, MAXNNZ);
    if (lane == 0) g_nnz[row] = nnz;
    int npad = (nnz + 7) & ~7;
    if (nnz + lane < npad) pbase[nnz + lane] = make_float2(0.f, 0.f);

    __syncthreads();
    for (int tt = tid; tt < N; tt += 512) atomicAdd(&g_Dsum[b*N + tt], Dpart[tt]);
}

// ---------------- C: invD = 1/(N+Dsum); c[b,o] += sum_j invD[j]*h[j,o] ----------------
__global__ void k_cvec() {
    __shared__ float inv_s[64];
    __shared__ float part[512];
    int tid = threadIdx.x;
    int b  = blockIdx.x >> 5;
    int j0 = (blockIdx.x & 31) * 64;

    if (tid < 64) {
        float v = 1.f / ((float)N + g_Dsum[b*N + j0 + tid]);
        g_invD[b*N + j0 + tid] = v;
        inv_s[tid] = v;
    }
    __syncthreads();

    int r = tid >> 6, o = tid & 63;
    float acc = 0.f;
#pragma unroll
    for (int q = 0; q < 8; q++) {
        int jj = q*8 + r;
        acc += inv_s[jj] * g_h[(size_t)(b*N + j0 + jj)*F + o];
    }
    part[tid] = acc;
    __syncthreads();
    if (tid < 64) {
        float s = 0.f;
#pragma unroll
        for (int q = 0; q < 8; q++) s += part[q*64 + tid];
        atomicAdd(&g_c[b*F + tid], s);
    }
}

// ---------------- D: sparse gather + epilogue (bias, residual, ELU) ----------------
// block = 256 threads = 8 warps = 8 rows (same batch). invD + pre-scaled pairs in smem.
__global__ void k_out(const float* __restrict__ in, const float* __restrict__ bias,
                      float* __restrict__ out) {
    __shared__ float  inv_s[N];                    // 8 KB
    __shared__ float4 pairs_s[8 * (MAXNNZ/2)];     // 16 KB: (joff0,w0,joff1,w1)
    int tid = threadIdx.x;
    int w = tid >> 5, lane = tid & 31;
    int rowBase = blockIdx.x * 8;
    int b = rowBase >> 11;

    // stage invD for this batch (coalesced)
    {
        const float4* invDv = (const float4*)(g_invD + b*N);
        float4* inv_s4 = (float4*)inv_s;
        for (int t = tid; t < N/4; t += 256) inv_s4[t] = invDv[t];
    }
    __syncthreads();

    // stage this warp's pair slab, pre-scaling weight and pre-baking float2 offset
    int row = rowBase + w;
    int i = row & (N - 1);
    int npad = (g_nnz[row] + 7) & ~7;
    {
        const float2* __restrict__ pbase = g_pairs + (size_t)row * MAXNNZ;
        float2* ps2 = (float2*)(pairs_s + w * (MAXNNZ/2));
        for (int t = lane; t < npad; t += 32) {
            float2 pr = pbase[t];
            int j = __float_as_int(pr.x);
            ps2[t] = make_float2(__int_as_float(j * 32), pr.y * inv_s[j]);
        }
    }
    __syncwarp();

    const float4* __restrict__ ps4 = pairs_s + w * (MAXNNZ/2);
    const float2* __restrict__ hb2 = (const float2*)(g_h + (size_t)b*N*F);

    float accx = 0.f, accy = 0.f;
    int nq = npad >> 1;                            // float4 count (multiple of 4)
#pragma unroll 1
    for (int k0 = 0; k0 < nq; k0 += 4) {
#pragma unroll
        for (int u = 0; u < 4; u++) {
            float4 pq = ps4[k0 + u];               // uniform LDS.128: 2 pairs
            int j0 = __float_as_int(pq.x);
            int j1 = __float_as_int(pq.z);
            float2 h0 = hb2[j0 + lane];
            float2 h1 = hb2[j1 + lane];
            accx += pq.y * h0.x;
            accy += pq.y * h0.y;
            accx += pq.w * h1.x;
            accy += pq.w * h1.y;
        }
    }

    int oidx = row * F + 2*lane;
    float2 cv = *(const float2*)(g_c + b*F + 2*lane);
    float2 bv = *(const float2*)(bias + i*F + 2*lane);
    float2 iv = *(const float2*)(in + oidx);
    float v0 = accx + cv.x + bv.x + iv.x;
    float v1 = accy + cv.y + bv.y + iv.y;
    float2 res;
    res.x = (v0 > 0.f) ? v0 : expm1f(v0);
    res.y = (v1 > 0.f) ? v1 : expm1f(v1);
    *(float2*)(out + oidx) = res;
}

// ---------------- launch ----------------
extern "C" void kernel_launch(void* const* d_in, const int* in_sizes, int n_in,
                              void* d_out, int out_size) {
    const float* input = (const float*)d_in[0];
    const float* adj   = (const float*)d_in[1];
    const float* W     = (const float*)d_in[2];
    const float* a1    = (const float*)d_in[3];
    const float* a2    = (const float*)d_in[4];
    const float* bias  = (const float*)d_in[5];
    float* out = (float*)d_out;

    k_hproj<<<BN/8,  512>>>(input, W, a1, a2);
    k_scan <<<BN/16, 512>>>(adj);
    k_cvec <<<B*32,  512>>>();
    k_out  <<<BN/8,  256>>>(input, bias, out);
}

// round 4
// speedup vs baseline: 1.6741x; 1.0043x over previous
#include <cuda_runtime.h>
#include <cuda_bf16.h>

#define B 8
#define N 2048
#define F 64
#define MAXNNZ 256
#define BN (B*N)  // 16384
#define LRELU_SLOPE 0.2f

// ---- scratch (static device arrays; re-initialized every launch) ----
__device__ float          g_h[BN*F];               // 4 MB fp32 h (k_cvec path)
__device__ __nv_bfloat16  g_hb[BN*F];              // 2 MB bf16 h (k_out gather path)
__device__ float  g_f1[BN];
__device__ float  g_f2[BN];
__device__ float  g_Dsum[BN];
__device__ float  g_invD[BN];
__device__ float  g_c[B*F];
__device__ int    g_nnz[BN];
__device__ float2 g_pairs[(size_t)BN*MAXNNZ];      // (j as int bits, p), zero-padded to %8

// ---------------- A: h = input@W (fp32 + bf16), f1/f2, zero accumulators ----------------
__global__ void k_hproj(const float* __restrict__ in, const float* __restrict__ W,
                        const float* __restrict__ a1, const float* __restrict__ a2) {
    __shared__ float Ws[F*F];
    __shared__ float a1s[F], a2s[F];
    __shared__ float ins[8*F];
    __shared__ float hs[8*F];
    int tid = threadIdx.x;
    int rowBase = blockIdx.x * 8;

    if (blockIdx.x < 32) g_Dsum[blockIdx.x * 512 + tid] = 0.f;
    if (blockIdx.x == 32 && tid < B*F) g_c[tid] = 0.f;

    for (int t = tid; t < F*F; t += 512) Ws[t] = W[t];
    if (tid < F) { a1s[tid] = a1[tid]; a2s[tid] = a2[tid]; }
    ins[tid] = in[rowBase*F + tid];
    __syncthreads();

    int r = tid >> 6, o = tid & 63;
    float acc = 0.f;
#pragma unroll
    for (int f = 0; f < F; f++) acc += ins[r*F + f] * Ws[f*F + o];
    g_h[(rowBase + r)*F + o]  = acc;
    g_hb[(rowBase + r)*F + o] = __float2bfloat16(acc);
    hs[tid] = acc;
    __syncthreads();

    int w = tid >> 5, lane = tid & 31;
    if (w < 8) {
        float v1 = hs[w*F + lane]*a1s[lane] + hs[w*F + lane + 32]*a1s[lane + 32];
        float v2 = hs[w*F + lane]*a2s[lane] + hs[w*F + lane + 32]*a2s[lane + 32];
#pragma unroll
        for (int off = 16; off; off >>= 1) {
            v1 += __shfl_down_sync(0xffffffffu, v1, off);
            v2 += __shfl_down_sync(0xffffffffu, v2, off);
        }
        if (lane == 0) { g_f1[rowBase + w] = v1; g_f2[rowBase + w] = v2; }
    }
}

// ---------------- B: stream adj once; compact nonzeros; accumulate D ----------------
__global__ void k_scan(const float* __restrict__ adj) {
    __shared__ float  Dpart[N];
    __shared__ float4 f2s4[N/4];
    int tid = threadIdx.x;
    int b  = blockIdx.x >> 7;
    int i0 = (blockIdx.x & 127) * 16;

    for (int t = tid; t < N; t += 512) Dpart[t] = 0.f;
    float* f2s = (float*)f2s4;
    for (int t = tid; t < N; t += 512) f2s[t] = g_f2[b*N + t];
    __syncthreads();

    int w = tid >> 5, lane = tid & 31;
    int row = b*N + i0 + w;
    float f1i = g_f1[row];
    const float4* __restrict__ arow = (const float4*)(adj + (size_t)row * N);
    float2* pbase = g_pairs + (size_t)row * MAXNNZ;
    unsigned lmask = (1u << lane) - 1u;
    int nnz = 0;

    int t = lane;
    float4 a = arow[t];
#pragma unroll 1
    for (int it = 0; it < 16; it++) {
        float4 anext;
        if (it < 15) anext = arow[t + 32];
        float4 f2v = f2s4[t];
#pragma unroll
        for (int k = 0; k < 4; k++) {
            float av = (k==0)?a.x:(k==1)?a.y:(k==2)?a.z:a.w;
            float fv = (k==0)?f2v.x:(k==1)?f2v.y:(k==2)?f2v.z:f2v.w;
            bool pred = (av != 0.f);
            unsigned m = __ballot_sync(0xffffffffu, pred);
            if (pred) {
                float e = f1i + fv;
                e = (e >= 0.f) ? e : LRELU_SLOPE * e;
                float p = __expf(av * e) - 1.f;
                int slot = nnz + __popc(m & lmask);
                if (slot < MAXNNZ)
                    pbase[slot] = make_float2(__int_as_float(4*t + k), p);
                atomicAdd(&Dpart[4*t + k], p);
            }
            nnz += __popc(m);
        }
        a = anext; t += 32;
    }
    nnz = min(nnz, MAXNNZ);
    if (lane == 0) g_nnz[row] = nnz;
    int npad = (nnz + 7) & ~7;
    if (nnz + lane < npad) pbase[nnz + lane] = make_float2(0.f, 0.f);

    __syncthreads();
    for (int tt = tid; tt < N; tt += 512) atomicAdd(&g_Dsum[b*N + tt], Dpart[tt]);
}

// ---------------- C: invD = 1/(N+Dsum); c[b,o] += sum_j invD[j]*h[j,o] ----------------
__global__ void k_cvec() {
    __shared__ float inv_s[64];
    __shared__ float part[512];
    int tid = threadIdx.x;
    int b  = blockIdx.x >> 5;
    int j0 = (blockIdx.x & 31) * 64;

    if (tid < 64) {
        float v = 1.f / ((float)N + g_Dsum[b*N + j0 + tid]);
        g_invD[b*N + j0 + tid] = v;
        inv_s[tid] = v;
    }
    __syncthreads();

    int r = tid >> 6, o = tid & 63;
    float acc = 0.f;
#pragma unroll
    for (int q = 0; q < 8; q++) {
        int jj = q*8 + r;
        acc += inv_s[jj] * g_h[(size_t)(b*N + j0 + jj)*F + o];
    }
    part[tid] = acc;
    __syncthreads();
    if (tid < 64) {
        float s = 0.f;
#pragma unroll
        for (int q = 0; q < 8; q++) s += part[q*64 + tid];
        atomicAdd(&g_c[b*F + tid], s);
    }
}

// ---------------- D: sparse bf16 gather + epilogue ----------------
// block = 512 threads = 16 warps = 16 rows (same batch); grid = BN/16.
__global__ void k_out(const float* __restrict__ in, const float* __restrict__ bias,
                      float* __restrict__ out) {
    __shared__ float  inv_s[N];                    // 8 KB
    __shared__ float4 pairs_s[16 * (MAXNNZ/2)];    // 32 KB: (joff0,w0,joff1,w1)
    int tid = threadIdx.x;
    int w = tid >> 5, lane = tid & 31;
    int rowBase = blockIdx.x * 16;
    int b = rowBase >> 11;

    // stage invD for this batch (coalesced; one float4 per thread)
    {
        const float4* invDv = (const float4*)(g_invD + b*N);
        ((float4*)inv_s)[tid] = invDv[tid];
    }
    __syncthreads();

    // stage this warp's pair slab; pre-scale weight, pre-bake bf16x2 row offset (j*32)
    int row = rowBase + w;
    int i = row & (N - 1);
    int npad = (g_nnz[row] + 7) & ~7;
    {
        const float2* __restrict__ pbase = g_pairs + (size_t)row * MAXNNZ;
        float2* ps2 = (float2*)(pairs_s + w * (MAXNNZ/2));
        for (int t = lane; t < npad; t += 32) {
            float2 pr = pbase[t];
            int j = __float_as_int(pr.x);
            ps2[t] = make_float2(__int_as_float(j * 32), pr.y * inv_s[j]);
        }
    }
    __syncwarp();

    const float4* __restrict__ ps4 = pairs_s + w * (MAXNNZ/2);
    const __nv_bfloat162* __restrict__ hb =
        (const __nv_bfloat162*)g_hb + (size_t)b * N * 32;

    float accx = 0.f, accy = 0.f;
    int nq = npad >> 1;
#pragma unroll 1
    for (int k0 = 0; k0 < nq; k0 += 4) {
#pragma unroll
        for (int u = 0; u < 4; u++) {
            float4 pq = ps4[k0 + u];               // uniform LDS.128: 2 pairs
            int j0 = __float_as_int(pq.x);
            int j1 = __float_as_int(pq.z);
            float2 f0 = __bfloat1622float2(hb[j0 + lane]);   // 128B gather (1 wf)
            float2 f1 = __bfloat1622float2(hb[j1 + lane]);
            accx += pq.y * f0.x;
            accy += pq.y * f0.y;
            accx += pq.w * f1.x;
            accy += pq.w * f1.y;
        }
    }

    int oidx = row * F + 2*lane;
    float2 cv = *(const float2*)(g_c + b*F + 2*lane);
    float2 bv = *(const float2*)(bias + i*F + 2*lane);
    float2 iv = *(const float2*)(in + oidx);
    float v0 = accx + cv.x + bv.x + iv.x;
    float v1 = accy + cv.y + bv.y + iv.y;
    float2 res;
    res.x = (v0 > 0.f) ? v0 : expm1f(v0);
    res.y = (v1 > 0.f) ? v1 : expm1f(v1);
    *(float2*)(out + oidx) = res;
}

// ---------------- launch ----------------
extern "C" void kernel_launch(void* const* d_in, const int* in_sizes, int n_in,
                              void* d_out, int out_size) {
    const float* input = (const float*)d_in[0];
    const float* adj   = (const float*)d_in[1];
    const float* W     = (const float*)d_in[2];
    const float* a1    = (const float*)d_in[3];
    const float* a2    = (const float*)d_in[4];
    const float* bias  = (const float*)d_in[5];
    float* out = (float*)d_out;

    k_hproj<<<BN/8,  512>>>(input, W, a1, a2);
    k_scan <<<BN/16, 512>>>(adj);
    k_cvec <<<B*32,  512>>>();
    k_out  <<<BN/16, 512>>>(input, bias, out);
}